// round 2
// baseline (speedup 1.0000x reference)
#include <cuda_runtime.h>
#include <cuda_bf16.h>

// Retrace loss, single fused kernel.
//  per row b (B=4096), stride S=1025, T=1024:
//    c[k]   = clip(tp[b,k]/bp[b,k], 1e-10, 1.0)
//    A[j] = r[b,j+1] + 0.99*eQ[b,j+2] - (0.99*c[j+2])*tQ[b,j+2]   (j=0..1022)
//    B[j] = 0.99*c[j+2]
//    y[1023] = Q[b,1024];  y[j] = A[j] + B[j]*y[j+1]
//    loss += sum_j (Q[b,j]-y[j])^2   (j=0..1023, y[1023]=Q[b,1024])
//  out = loss / (4096*1024)
//
// Backward recurrence parallelized as a suffix scan of affine maps:
//   (A1,B1) o (A2,B2) = (A1 + B1*A2, B1*B2)
// Cross-block: per-block partial sums in a __device__ array + self-resetting
// wrap-around atomicInc counter; last block reduces and writes d_out.

#define S_STRIDE 1025
#define T_LEN    1024
#define NROWS    4096
#define GAMMA_F  0.99f
#define EPS_F    1e-10f
#define NTHREADS 256
#define ITEMS    4   // 256*4 = 1024 slots; slot 1023 = identity pad

__device__ double   g_part[NROWS];
__device__ unsigned g_count = 0;   // wraps 0..4095 via atomicInc -> deterministic across replays

struct Aff { float a, b; };

__device__ __forceinline__ Aff comp(Aff f, Aff g) {
    // f o g : apply g first, then f
    Aff r;
    r.a = fmaf(f.b, g.a, f.a);
    r.b = f.b * g.b;
    return r;
}

__global__ void __launch_bounds__(NTHREADS)
retrace_kernel(const float* __restrict__ Q,
               const float* __restrict__ eQ,
               const float* __restrict__ tQ,
               const float* __restrict__ r,
               const float* __restrict__ tp,
               const float* __restrict__ bp,
               float* __restrict__ out)
{
    const int row = blockIdx.x;
    const long base = (long)row * S_STRIDE;
    const int t = threadIdx.x;
    const unsigned lane = t & 31u;
    const unsigned w = t >> 5;
    const int j0 = t * ITEMS;

    // ---- front-batched loads (high MLP): 4 consecutive cols per thread, coalesced
    float qv[ITEMS], rv[ITEMS], ev[ITEMS], tqv[ITEMS], ptv[ITEMS], pbv[ITEMS];
#pragma unroll
    for (int k = 0; k < ITEMS; k++) {
        const int j = j0 + k;
        qv[k] = __ldg(&Q[base + j]);
        if (j < T_LEN - 1) {
            rv[k]  = __ldg(&r [base + j + 1]);
            ev[k]  = __ldg(&eQ[base + j + 2]);
            tqv[k] = __ldg(&tQ[base + j + 2]);
            ptv[k] = __ldg(&tp[base + j + 2]);
            pbv[k] = __ldg(&bp[base + j + 2]);
        }
    }
    const float init = __ldg(&Q[base + T_LEN]);  // Q[b,1024]

    // ---- build local affine maps
    Aff loc[ITEMS];
#pragma unroll
    for (int k = 0; k < ITEMS; k++) {
        const int j = j0 + k;
        if (j < T_LEN - 1) {
            const float c = fminf(fmaxf(__fdividef(ptv[k], pbv[k]), EPS_F), 1.0f);
            const float B = GAMMA_F * c;
            loc[k].b = B;
            loc[k].a = fmaf(GAMMA_F, ev[k], rv[k]) - B * tqv[k];
        } else {
            loc[k].a = 0.0f; loc[k].b = 1.0f;   // identity pad (j == 1023)
        }
    }

    // ---- per-thread local suffix composition
    Aff suf[ITEMS];
    suf[ITEMS - 1] = loc[ITEMS - 1];
#pragma unroll
    for (int k = ITEMS - 2; k >= 0; k--) suf[k] = comp(loc[k], suf[k + 1]);

    // ---- warp-level inclusive suffix scan of thread aggregates
    Aff v = suf[0];
#pragma unroll
    for (int off = 1; off < 32; off <<= 1) {
        float oa = __shfl_down_sync(0xffffffffu, v.a, off);
        float ob = __shfl_down_sync(0xffffffffu, v.b, off);
        if (lane + off < 32) { Aff g; g.a = oa; g.b = ob; v = comp(v, g); }
    }

    // in-warp EXCLUSIVE suffix (threads lane+1..31)
    float ea = __shfl_down_sync(0xffffffffu, v.a, 1);
    float eb = __shfl_down_sync(0xffffffffu, v.b, 1);
    Aff inwexcl;
    if (lane == 31) { inwexcl.a = 0.0f; inwexcl.b = 1.0f; }
    else            { inwexcl.a = ea;   inwexcl.b = eb;   }

    __shared__ float sA[8], sB[8];   // warp inclusive totals
    __shared__ float wA[8], wB[8];   // per-warp exclusive suffixes
    if (lane == 0) { sA[w] = v.a; sB[w] = v.b; }
    __syncthreads();
    if (t == 0) {
        Aff acc; acc.a = 0.0f; acc.b = 1.0f;
        for (int ww = 7; ww >= 0; ww--) {
            wA[ww] = acc.a; wB[ww] = acc.b;
            Aff tot; tot.a = sA[ww]; tot.b = sB[ww];
            acc = comp(tot, acc);
        }
    }
    __syncthreads();

    Aff wex; wex.a = wA[w]; wex.b = wB[w];
    const Aff S = comp(inwexcl, wex);

    // ---- apply composed maps and accumulate squared error
    double lsum = 0.0;
#pragma unroll
    for (int k = 0; k < ITEMS; k++) {
        const Aff m = comp(suf[k], S);
        const float y = fmaf(m.b, init, m.a);
        const float d = qv[k] - y;
        lsum += (double)d * (double)d;
    }

    // ---- block reduction (double)
#pragma unroll
    for (int off = 16; off > 0; off >>= 1)
        lsum += __shfl_down_sync(0xffffffffu, lsum, off);
    __shared__ double ssum[8];
    if (lane == 0) ssum[w] = lsum;
    __syncthreads();

    __shared__ bool s_last;
    if (t == 0) {
        double x = 0.0;
#pragma unroll
        for (int i = 0; i < 8; i++) x += ssum[i];
        g_part[row] = x;
        __threadfence();
        unsigned old = atomicInc(&g_count, NROWS - 1);  // wraps to 0 after 4096 arrivals
        s_last = (old == NROWS - 1);
    }
    __syncthreads();

    // ---- last block reduces all partials and writes output
    if (s_last) {
        double x = 0.0;
        for (int i = t; i < NROWS; i += NTHREADS)
            x += __ldcg(&g_part[i]);
#pragma unroll
        for (int off = 16; off > 0; off >>= 1)
            x += __shfl_down_sync(0xffffffffu, x, off);
        __shared__ double fsum[8];
        if (lane == 0) fsum[w] = x;
        __syncthreads();
        if (t == 0) {
            double tot = 0.0;
#pragma unroll
            for (int i = 0; i < 8; i++) tot += fsum[i];
            out[0] = (float)(tot / (double)((long long)NROWS * T_LEN));
        }
    }
}

extern "C" void kernel_launch(void* const* d_in, const int* in_sizes, int n_in,
                              void* d_out, int out_size)
{
    const float* Q   = (const float*)d_in[0];
    const float* eQ  = (const float*)d_in[1];
    const float* tQ  = (const float*)d_in[2];
    const float* r   = (const float*)d_in[3];
    const float* tp  = (const float*)d_in[4];
    const float* bp  = (const float*)d_in[5];
    float* out = (float*)d_out;

    retrace_kernel<<<NROWS, NTHREADS>>>(Q, eQ, tQ, r, tp, bp, out);
}